// round 4
// baseline (speedup 1.0000x reference)
#include <cuda_runtime.h>
#include <math.h>
#include <stdint.h>

#define N_PROP 1024
#define C_FEAT 32
#define ROI 7
#define SR 6
#define SS 42
#define D_FEAT 1568
#define HID 2048
#define NMS_K 100
#define OUT_TOTAL 2600
#define NMS_THRF 0.01f

#define X_MIN (-40.0f)
#define Z_MAX (70.0f)
#define VOX (0.1f)

// ---------------- scratch ----------------------------------------------------
__device__ float g_imgbox[N_PROP * 4];
__device__ float g_bevbox[N_PROP * 4];
__device__ float g_roiA[N_PROP * D_FEAT];
__device__ float g_roiB[N_PROP * D_FEAT];
__device__ float g_fused[N_PROP * D_FEAT];
__device__ float g_h1[N_PROP * HID];
__device__ float g_h2[N_PROP * HID];
__device__ float g_heads[N_PROP * 14];
__device__ float g_obj_soft[N_PROP * 2];
__device__ float g_pred[N_PROP * 6];
__device__ float g_predbev[N_PROP * 4];
__device__ float g_scores[N_PROP];
__device__ float g_orient[N_PROP];
__device__ int   g_idx[NMS_K];

// ---------------- cp.async helpers -------------------------------------------
#define CP_ASYNC16(dst_u32, src_ptr) \
    asm volatile("cp.async.cg.shared.global [%0], [%1], 16;" :: "r"(dst_u32), "l"(src_ptr))
#define CP_COMMIT() asm volatile("cp.async.commit_group;")
#define CP_WAIT_ALL() asm volatile("cp.async.wait_group 0;")

__device__ __forceinline__ unsigned long long dup2(float f) {
    unsigned long long r;
    asm("mov.b64 %0, {%1, %1};" : "=l"(r) : "f"(f));
    return r;
}

// ---------------- projections ------------------------------------------------
__global__ void project_kernel(const float* __restrict__ anchors,
                               const float* __restrict__ calib,
                               const int* __restrict__ image_shape)
{
    int n = blockIdx.x * blockDim.x + threadIdx.x;
    if (n >= N_PROP) return;
    const float* a = anchors + n * 6;
    float x = a[0], y = a[1], z = a[2];
    float dx = a[3], dy = a[4], dz = a[5];

    g_bevbox[n*4+0] = (x - dx*0.5f - X_MIN) / VOX;
    g_bevbox[n*4+1] = (Z_MAX - (z + dz*0.5f)) / VOX;
    g_bevbox[n*4+2] = (x + dx*0.5f - X_MIN) / VOX;
    g_bevbox[n*4+3] = (Z_MAX - (z - dz*0.5f)) / VOX;

    float P[12];
#pragma unroll
    for (int i = 0; i < 12; i++) P[i] = calib[i];
    float Hf = (float)image_shape[0];
    float Wf = (float)image_shape[1];

    float umin = 1e30f, umax = -1e30f, vmin = 1e30f, vmax = -1e30f;
#pragma unroll
    for (int k = 0; k < 8; k++) {
        float sx = (k & 4) ? 1.f : -1.f;
        float sy = (k & 2) ? 1.f : -1.f;
        float sz = (k & 1) ? 1.f : -1.f;
        float cx = x + sx * dx * 0.5f;
        float cy = y + sy * dy * 0.5f;
        float cz = z + sz * dz * 0.5f;
        float px = P[0]*cx + P[1]*cy + P[2]*cz + P[3];
        float py = P[4]*cx + P[5]*cy + P[6]*cz + P[7];
        float pz = P[8]*cx + P[9]*cy + P[10]*cz + P[11];
        float zz = fmaxf(pz, 0.1f);
        float u = px / zz, v = py / zz;
        umin = fminf(umin, u); umax = fmaxf(umax, u);
        vmin = fminf(vmin, v); vmax = fmaxf(vmax, v);
    }
    g_imgbox[n*4+0] = fminf(fmaxf(umin, 0.f), Wf);
    g_imgbox[n*4+1] = fminf(fmaxf(vmin, 0.f), Hf);
    g_imgbox[n*4+2] = fminf(fmaxf(umax, 0.f), Wf);
    g_imgbox[n*4+3] = fminf(fmaxf(vmax, 0.f), Hf);
}

// ---------------- ROI align (both maps in one grid) --------------------------
__global__ void roi_kernel(const float* __restrict__ img_feat,
                           const float* __restrict__ bev_feat)
{
    int b = blockIdx.x;
    int isImg = (b < N_PROP);
    int n = b & (N_PROP - 1);

    const float* feat  = isImg ? img_feat : bev_feat;
    const float* boxes = isImg ? g_imgbox : g_bevbox;
    float* outp        = isImg ? g_roiA   : g_roiB;
    int H = isImg ? 360 : 700;
    int W = isImg ? 1200 : 800;

    __shared__ int   sx0[SS], sx1[SS], sy0[SS], sy1[SS];
    __shared__ float swx[SS], swy[SS];

    int t = threadIdx.x;
    if (t < SS) {
        float bx1 = boxes[n*4+0] - 0.5f;
        float bx2 = boxes[n*4+2] - 0.5f;
        float g = ((float)t + 0.5f) / (float)SS;
        float xs = bx1 + g * (bx2 - bx1);
        float xf = fminf(fmaxf(floorf(xs), 0.f), (float)(W - 1));
        swx[t] = fminf(fmaxf(xs - xf, 0.f), 1.f);
        int xi = (int)xf;
        sx0[t] = xi;
        sx1[t] = min(xi + 1, W - 1);
    } else if (t < 2 * SS) {
        int tt = t - SS;
        float by1 = boxes[n*4+1] - 0.5f;
        float by2 = boxes[n*4+3] - 0.5f;
        float g = ((float)tt + 0.5f) / (float)SS;
        float ys = by1 + g * (by2 - by1);
        float yf = fminf(fmaxf(floorf(ys), 0.f), (float)(H - 1));
        swy[tt] = fminf(fmaxf(ys - yf, 0.f), 1.f);
        int yi = (int)yf;
        sy0[tt] = yi;
        sy1[tt] = min(yi + 1, H - 1);
    }
    __syncthreads();

    for (int o = t; o < D_FEAT; o += blockDim.x) {
        int c = o / 49;
        int r = o % 49;
        int py = (r / 7) * SR;
        int px = (r % 7) * SR;
        const float* fc = feat + (size_t)c * H * W;

        // hoist x coords to registers
        int lx0[SR], lx1[SR];
        float lwx[SR];
#pragma unroll
        for (int sx = 0; sx < SR; sx++) {
            lx0[sx] = sx0[px + sx];
            lx1[sx] = sx1[px + sx];
            lwx[sx] = swx[px + sx];
        }

        float sum = 0.f;
#pragma unroll
        for (int sy = 0; sy < SR; sy++) {
            int yi = sy0[py + sy], yj = sy1[py + sy];
            float wy = swy[py + sy];
            const float* row0 = fc + (size_t)yi * W;
            const float* row1 = fc + (size_t)yj * W;
#pragma unroll
            for (int sx = 0; sx < SR; sx++) {
                int x0 = lx0[sx], x1 = lx1[sx];
                float w = lwx[sx];
                float f00 = row0[x0], f01 = row0[x1];
                float f10 = row1[x0], f11 = row1[x1];
                float top = f00 + (f01 - f00) * w;
                float bot = f10 + (f11 - f10) * w;
                sum += top + (bot - top) * wy;
            }
        }
        outp[(size_t)n * D_FEAT + o] = sum * (1.f / 36.f);
    }
}

// ---------------- fuse --------------------------------------------------------
__global__ void fuse_kernel(const float* __restrict__ mi,
                            const float* __restrict__ mb)
{
    int i = blockIdx.x * blockDim.x + threadIdx.x;
    if (i >= N_PROP * D_FEAT) return;
    float a = mi[0], bm = mb[0];
    float inv = 1.f / (a + bm);
    g_fused[i] = (g_roiA[i] * a + g_roiB[i] * bm) * inv;
}

// ---------------- SGEMM: FFMA2, dup-A smem, BK=32, cp.async B -----------------
// BM=64, BN=128, BK=32, 128 threads. Dynamic smem 64KB.
template<int RELU>
__global__ __launch_bounds__(128)
void gemm_kernel(const float* __restrict__ A, const float* __restrict__ B,
                 const float* __restrict__ bias, float* __restrict__ C,
                 int M, int N, int K)
{
    const int BM = 64, BN = 128, BK = 32;
    extern __shared__ char smem_raw[];
    // As2: [2][BK][BM] u64 (duplicated pairs), 32KB; Bs: [2][BK][BN] f32, 32KB
    unsigned long long (*As2)[BK][BM] =
        reinterpret_cast<unsigned long long (*)[BK][BM]>(smem_raw);
    float (*Bs)[BK][BN] =
        reinterpret_cast<float (*)[BK][BN]>(smem_raw + 2 * BK * BM * 8);

    int tid = threadIdx.x;
    int tx = tid & 15;      // 16 col groups of 8
    int ty = tid >> 4;      // 8 row groups of 8
    int m0 = blockIdx.y * BM;
    int n0 = blockIdx.x * BN;

    // A: 64x32 floats = 512 float4; 4 per thread
    int a_row[4], a_kc[4];
#pragma unroll
    for (int l = 0; l < 4; l++) {
        int idx = tid + l * 128;
        a_row[l] = idx >> 3;
        a_kc[l]  = (idx & 7) << 2;
    }
    // B: 32x128 floats = 1024 float4; 8 per thread (cp.async)
    int b_kk[8], b_c4[8];
#pragma unroll
    for (int l = 0; l < 8; l++) {
        int idx = tid + l * 128;
        b_kk[l] = idx >> 5;
        b_c4[l] = (idx & 31) << 2;
    }
    uint32_t bs_base = (uint32_t)__cvta_generic_to_shared(&Bs[0][0][0]);

    unsigned long long acc2[8][4];
#pragma unroll
    for (int i = 0; i < 8; i++)
#pragma unroll
        for (int j = 0; j < 4; j++) acc2[i][j] = 0ULL;

    int nt = K / BK;

    // prologue: tile 0
    {
#pragma unroll
        for (int l = 0; l < 8; l++) {
            uint32_t dst = bs_base + (uint32_t)((b_kk[l] * BN + b_c4[l]) * 4);
            const float* src = B + (size_t)b_kk[l] * N + n0 + b_c4[l];
            CP_ASYNC16(dst, src);
        }
        CP_COMMIT();
#pragma unroll
        for (int l = 0; l < 4; l++) {
            float4 v = *reinterpret_cast<const float4*>(
                A + (size_t)(m0 + a_row[l]) * K + a_kc[l]);
            As2[0][a_kc[l] + 0][a_row[l]] = dup2(v.x);
            As2[0][a_kc[l] + 1][a_row[l]] = dup2(v.y);
            As2[0][a_kc[l] + 2][a_row[l]] = dup2(v.z);
            As2[0][a_kc[l] + 3][a_row[l]] = dup2(v.w);
        }
        CP_WAIT_ALL();
    }
    __syncthreads();

    int buf = 0;
    for (int t = 0; t < nt; t++) {
        bool more = (t + 1 < nt);
        float4 ra[4];
        if (more) {
            int k0n = (t + 1) * BK;
            int nb = buf ^ 1;
#pragma unroll
            for (int l = 0; l < 8; l++) {
                uint32_t dst = bs_base +
                    (uint32_t)(((nb * BK + b_kk[l]) * BN + b_c4[l]) * 4);
                const float* src = B + (size_t)(k0n + b_kk[l]) * N + n0 + b_c4[l];
                CP_ASYNC16(dst, src);
            }
            CP_COMMIT();
#pragma unroll
            for (int l = 0; l < 4; l++)
                ra[l] = *reinterpret_cast<const float4*>(
                    A + (size_t)(m0 + a_row[l]) * K + k0n + a_kc[l]);
        }

        // compute 32 kk
#pragma unroll
        for (int kk = 0; kk < BK; kk++) {
            const ulonglong2* ap =
                reinterpret_cast<const ulonglong2*>(&As2[buf][kk][ty * 8]);
            ulonglong2 a0 = ap[0], a1 = ap[1], a2 = ap[2], a3 = ap[3];
            ulonglong2 b01 = *reinterpret_cast<const ulonglong2*>(&Bs[buf][kk][tx * 8]);
            ulonglong2 b23 = *reinterpret_cast<const ulonglong2*>(&Bs[buf][kk][tx * 8 + 4]);
            unsigned long long ad[8] = {a0.x, a0.y, a1.x, a1.y, a2.x, a2.y, a3.x, a3.y};
            unsigned long long bp[4] = {b01.x, b01.y, b23.x, b23.y};
#pragma unroll
            for (int i = 0; i < 8; i++) {
                asm("fma.rn.f32x2 %0, %1, %2, %0;" : "+l"(acc2[i][0]) : "l"(ad[i]), "l"(bp[0]));
                asm("fma.rn.f32x2 %0, %1, %2, %0;" : "+l"(acc2[i][1]) : "l"(ad[i]), "l"(bp[1]));
                asm("fma.rn.f32x2 %0, %1, %2, %0;" : "+l"(acc2[i][2]) : "l"(ad[i]), "l"(bp[2]));
                asm("fma.rn.f32x2 %0, %1, %2, %0;" : "+l"(acc2[i][3]) : "l"(ad[i]), "l"(bp[3]));
            }
        }

        if (more) {
            int nb = buf ^ 1;
#pragma unroll
            for (int l = 0; l < 4; l++) {
                As2[nb][a_kc[l] + 0][a_row[l]] = dup2(ra[l].x);
                As2[nb][a_kc[l] + 1][a_row[l]] = dup2(ra[l].y);
                As2[nb][a_kc[l] + 2][a_row[l]] = dup2(ra[l].z);
                As2[nb][a_kc[l] + 3][a_row[l]] = dup2(ra[l].w);
            }
            CP_WAIT_ALL();
            __syncthreads();
            buf = nb;
        }
    }

    // epilogue
    float4 bv0 = *reinterpret_cast<const float4*>(bias + n0 + tx * 8);
    float4 bv1 = *reinterpret_cast<const float4*>(bias + n0 + tx * 8 + 4);
#pragma unroll
    for (int i = 0; i < 8; i++) {
        int mrow = m0 + ty * 8 + i;
        float2 p0 = *reinterpret_cast<float2*>(&acc2[i][0]);
        float2 p1 = *reinterpret_cast<float2*>(&acc2[i][1]);
        float2 p2 = *reinterpret_cast<float2*>(&acc2[i][2]);
        float2 p3 = *reinterpret_cast<float2*>(&acc2[i][3]);
        float4 o0 = {p0.x + bv0.x, p0.y + bv0.y, p1.x + bv0.z, p1.y + bv0.w};
        float4 o1 = {p2.x + bv1.x, p2.y + bv1.y, p3.x + bv1.z, p3.y + bv1.w};
        if (RELU) {
            o0.x = fmaxf(o0.x, 0.f); o0.y = fmaxf(o0.y, 0.f);
            o0.z = fmaxf(o0.z, 0.f); o0.w = fmaxf(o0.w, 0.f);
            o1.x = fmaxf(o1.x, 0.f); o1.y = fmaxf(o1.y, 0.f);
            o1.z = fmaxf(o1.z, 0.f); o1.w = fmaxf(o1.w, 0.f);
        }
        *reinterpret_cast<float4*>(C + (size_t)mrow * N + n0 + tx * 8)     = o0;
        *reinterpret_cast<float4*>(C + (size_t)mrow * N + n0 + tx * 8 + 4) = o1;
    }
}

// ---------------- heads: warp per row, float2 W loads -------------------------
__global__ void heads_kernel(const float* __restrict__ Wc, const float* __restrict__ bc,
                             const float* __restrict__ Wo, const float* __restrict__ bo,
                             const float* __restrict__ Wa, const float* __restrict__ ba)
{
    int warp = threadIdx.x >> 5;
    int lane = threadIdx.x & 31;
    int row = blockIdx.x * 8 + warp;

    const float2* Wc2 = reinterpret_cast<const float2*>(Wc);
    const float2* Wo2 = reinterpret_cast<const float2*>(Wo);
    const float2* Wa2 = reinterpret_cast<const float2*>(Wa);

    float acc[14];
#pragma unroll
    for (int c = 0; c < 14; c++) acc[c] = 0.f;

    const float* h = g_h2 + (size_t)row * HID;
    for (int k = lane; k < HID; k += 32) {
        float hv = h[k];
        float2 cw = Wc2[k];
        acc[0] = fmaf(hv, cw.x, acc[0]);
        acc[1] = fmaf(hv, cw.y, acc[1]);
        const float2* wo = Wo2 + (size_t)k * 5;
#pragma unroll
        for (int j = 0; j < 5; j++) {
            float2 ov = wo[j];
            acc[2 + 2*j]     = fmaf(hv, ov.x, acc[2 + 2*j]);
            acc[2 + 2*j + 1] = fmaf(hv, ov.y, acc[2 + 2*j + 1]);
        }
        float2 aw = Wa2[k];
        acc[12] = fmaf(hv, aw.x, acc[12]);
        acc[13] = fmaf(hv, aw.y, acc[13]);
    }
#pragma unroll
    for (int c = 0; c < 14; c++) {
#pragma unroll
        for (int off = 16; off > 0; off >>= 1)
            acc[c] += __shfl_down_sync(0xffffffffu, acc[c], off);
    }
    if (lane == 0) {
#pragma unroll
        for (int c = 0; c < 14; c++) {
            float b = (c < 2) ? bc[c] : (c < 12 ? bo[c-2] : ba[c-12]);
            g_heads[row*14 + c] = acc[c] + b;
        }
    }
}

// ---------------- post ---------------------------------------------------------
__global__ void post_kernel(const float* __restrict__ anchors)
{
    int n = blockIdx.x * blockDim.x + threadIdx.x;
    if (n >= N_PROP) return;
    const float* hd = g_heads + n * 14;
    float o0 = hd[0], o1 = hd[1];
    float m = fmaxf(o0, o1);
    float e0 = expf(o0 - m), e1 = expf(o1 - m);
    float inv = 1.f / (e0 + e1);
    g_obj_soft[n*2+0] = e0 * inv;
    g_obj_soft[n*2+1] = e1 * inv;
    g_scores[n] = o1;
    g_orient[n] = atan2f(hd[13], hd[12]);

    float p[6];
#pragma unroll
    for (int i = 0; i < 6; i++) {
        p[i] = anchors[n*6+i] + hd[2+i];
        g_pred[n*6+i] = p[i];
    }
    float x = p[0], z = p[2], dx = p[3], dz = p[5];
    g_predbev[n*4+0] = (x - dx*0.5f - X_MIN) / VOX;
    g_predbev[n*4+1] = (Z_MAX - (z + dz*0.5f)) / VOX;
    g_predbev[n*4+2] = (x + dx*0.5f - X_MIN) / VOX;
    g_predbev[n*4+3] = (Z_MAX - (z - dz*0.5f)) / VOX;
}

// ---------------- NMS: 256 threads, 4 boxes/thread ----------------------------
__global__ void nms_kernel()
{
    int t = threadIdx.x;    // 256 threads
    __shared__ float ss[N_PROP];
    __shared__ float sval[8];
    __shared__ int   sidx[8];
    __shared__ float sb[4];
    __shared__ int   scur;

    float bx1[4], by1[4], bx2[4], by2[4], bar[4];
#pragma unroll
    for (int i = 0; i < 4; i++) {
        int b = t + i * 256;
        bx1[i] = g_predbev[b*4+0];
        by1[i] = g_predbev[b*4+1];
        bx2[i] = g_predbev[b*4+2];
        by2[i] = g_predbev[b*4+3];
        bar[i] = (bx2[i] - bx1[i]) * (by2[i] - by1[i]);
        ss[b] = g_scores[b];
    }
    __syncthreads();

    int warp = t >> 5, lane = t & 31;
    for (int k = 0; k < NMS_K; k++) {
        float v = -INFINITY;
        int bi = N_PROP;
#pragma unroll
        for (int i = 0; i < 4; i++) {          // ascending idx: ties keep first
            int b = t + i * 256;
            float s = ss[b];
            if (s > v) { v = s; bi = b; }
        }
#pragma unroll
        for (int off = 16; off > 0; off >>= 1) {
            float ov = __shfl_down_sync(0xffffffffu, v, off);
            int   oi = __shfl_down_sync(0xffffffffu, bi, off);
            if (ov > v || (ov == v && oi < bi)) { v = ov; bi = oi; }
        }
        if (lane == 0) { sval[warp] = v; sidx[warp] = bi; }
        __syncthreads();
        if (t < 8) {
            v = sval[t]; bi = sidx[t];
#pragma unroll
            for (int off = 4; off > 0; off >>= 1) {
                float ov = __shfl_down_sync(0xffu, v, off, 8);
                int   oi = __shfl_down_sync(0xffu, bi, off, 8);
                if (ov > v || (ov == v && oi < bi)) { v = ov; bi = oi; }
            }
            if (t == 0) {
                scur = bi;
                g_idx[k] = bi;
                sb[0] = g_predbev[bi*4+0];
                sb[1] = g_predbev[bi*4+1];
                sb[2] = g_predbev[bi*4+2];
                sb[3] = g_predbev[bi*4+3];
            }
        }
        __syncthreads();
        float px1 = sb[0], py1 = sb[1], px2 = sb[2], py2 = sb[3];
        float parea = (px2 - px1) * (py2 - py1);
        int cur = scur;
#pragma unroll
        for (int i = 0; i < 4; i++) {
            int b = t + i * 256;
            float xx1 = fmaxf(bx1[i], px1);
            float yy1 = fmaxf(by1[i], py1);
            float xx2 = fminf(bx2[i], px2);
            float yy2 = fminf(by2[i], py2);
            float inter = fmaxf(xx2 - xx1, 0.f) * fmaxf(yy2 - yy1, 0.f);
            float iou = inter / (bar[i] + parea - inter + 1e-6f);
            if (iou > NMS_THRF || b == cur) ss[b] = -INFINITY;
        }
        __syncthreads();
    }
}

// ---------------- gather -------------------------------------------------------
__global__ void gather_kernel(float* __restrict__ out)
{
    int i = blockIdx.x * blockDim.x + threadIdx.x;
    if (i >= OUT_TOTAL) return;
    float v;
    if (i < 200) {
        int n = i / 2, c = i % 2;
        v = g_obj_soft[g_idx[n]*2 + c];
    } else if (i < 800) {
        int j = i - 200; int n = j / 6, c = j % 6;
        v = g_pred[g_idx[n]*6 + c];
    } else if (i < 1800) {
        int j = i - 800; int n = j / 10, c = j % 10;
        v = g_heads[g_idx[n]*14 + 2 + c];
    } else if (i < 2500) {
        int j = i - 1800; int n = j / 7, c = j % 7;
        v = (c < 6) ? g_pred[g_idx[n]*6 + c] : 0.f;
    } else {
        int n = i - 2500;
        v = g_orient[g_idx[n]];
    }
    out[i] = v;
}

// ---------------- launch --------------------------------------------------------
extern "C" void kernel_launch(void* const* d_in, const int* in_sizes, int n_in,
                              void* d_out, int out_size)
{
    const float* img_feat = (const float*)d_in[0];
    const float* bev_feat = (const float*)d_in[1];
    const float* anchors  = (const float*)d_in[2];
    const float* calib    = (const float*)d_in[3];
    const float* img_mask = (const float*)d_in[5];
    const float* bev_mask = (const float*)d_in[6];
    const float* W1 = (const float*)d_in[7];
    const float* b1 = (const float*)d_in[8];
    const float* W2 = (const float*)d_in[9];
    const float* b2 = (const float*)d_in[10];
    const float* Wc = (const float*)d_in[11];
    const float* bc = (const float*)d_in[12];
    const float* Wo = (const float*)d_in[13];
    const float* bo = (const float*)d_in[14];
    const float* Wa = (const float*)d_in[15];
    const float* ba = (const float*)d_in[16];
    const int* image_shape = (const int*)d_in[17];
    float* out = (float*)d_out;

    void *p_fused, *p_h1, *p_h2;
    cudaGetSymbolAddress(&p_fused, g_fused);
    cudaGetSymbolAddress(&p_h1, g_h1);
    cudaGetSymbolAddress(&p_h2, g_h2);

    const int GEMM_SMEM = 65536;
    cudaFuncSetAttribute(gemm_kernel<1>,
                         cudaFuncAttributeMaxDynamicSharedMemorySize, GEMM_SMEM);

    project_kernel<<<8, 128>>>(anchors, calib, image_shape);

    roi_kernel<<<2 * N_PROP, 256>>>(img_feat, bev_feat);
    fuse_kernel<<<(N_PROP * D_FEAT + 255) / 256, 256>>>(img_mask, bev_mask);

    dim3 g1(HID / 128, N_PROP / 64);
    gemm_kernel<1><<<g1, 128, GEMM_SMEM>>>((const float*)p_fused, W1, b1, (float*)p_h1,
                                           N_PROP, HID, D_FEAT);
    gemm_kernel<1><<<g1, 128, GEMM_SMEM>>>((const float*)p_h1, W2, b2, (float*)p_h2,
                                           N_PROP, HID, HID);

    heads_kernel<<<N_PROP / 8, 256>>>(Wc, bc, Wo, bo, Wa, ba);
    post_kernel<<<8, 128>>>(anchors);
    nms_kernel<<<1, 256>>>();
    gather_kernel<<<(OUT_TOTAL + 255) / 256, 256>>>(out);
}

// round 5
// speedup vs baseline: 1.1165x; 1.1165x over previous
#include <cuda_runtime.h>
#include <math.h>
#include <stdint.h>

#define N_PROP 1024
#define C_FEAT 32
#define ROI 7
#define SR 6
#define SS 42
#define D_FEAT 1568
#define HID 2048
#define NMS_K 100
#define OUT_TOTAL 2600
#define NMS_THRF 0.01f

#define X_MIN (-40.0f)
#define Z_MAX (70.0f)
#define VOX (0.1f)

// ---------------- scratch ----------------------------------------------------
__device__ float g_imgbox[N_PROP * 4];
__device__ float g_bevbox[N_PROP * 4];
__device__ float g_roiA[N_PROP * D_FEAT];
__device__ float g_roiB[N_PROP * D_FEAT];
__device__ float g_fused[N_PROP * D_FEAT];
__device__ float g_h1[N_PROP * HID];
__device__ float g_h2[N_PROP * HID];
__device__ float g_heads[N_PROP * 14];
__device__ float g_obj_soft[N_PROP * 2];
__device__ float g_pred[N_PROP * 6];
__device__ float g_predbev[N_PROP * 4];
__device__ float g_scores[N_PROP];
__device__ float g_orient[N_PROP];
__device__ int   g_idx[NMS_K];

// ---------------- projections ------------------------------------------------
__global__ void project_kernel(const float* __restrict__ anchors,
                               const float* __restrict__ calib,
                               const int* __restrict__ image_shape)
{
    int n = blockIdx.x * blockDim.x + threadIdx.x;
    if (n >= N_PROP) return;
    const float* a = anchors + n * 6;
    float x = a[0], y = a[1], z = a[2];
    float dx = a[3], dy = a[4], dz = a[5];

    g_bevbox[n*4+0] = (x - dx*0.5f - X_MIN) / VOX;
    g_bevbox[n*4+1] = (Z_MAX - (z + dz*0.5f)) / VOX;
    g_bevbox[n*4+2] = (x + dx*0.5f - X_MIN) / VOX;
    g_bevbox[n*4+3] = (Z_MAX - (z - dz*0.5f)) / VOX;

    float P[12];
#pragma unroll
    for (int i = 0; i < 12; i++) P[i] = calib[i];
    float Hf = (float)image_shape[0];
    float Wf = (float)image_shape[1];

    float umin = 1e30f, umax = -1e30f, vmin = 1e30f, vmax = -1e30f;
#pragma unroll
    for (int k = 0; k < 8; k++) {
        float sx = (k & 4) ? 1.f : -1.f;
        float sy = (k & 2) ? 1.f : -1.f;
        float sz = (k & 1) ? 1.f : -1.f;
        float cx = x + sx * dx * 0.5f;
        float cy = y + sy * dy * 0.5f;
        float cz = z + sz * dz * 0.5f;
        float px = P[0]*cx + P[1]*cy + P[2]*cz + P[3];
        float py = P[4]*cx + P[5]*cy + P[6]*cz + P[7];
        float pz = P[8]*cx + P[9]*cy + P[10]*cz + P[11];
        float zz = fmaxf(pz, 0.1f);
        float u = px / zz, v = py / zz;
        umin = fminf(umin, u); umax = fmaxf(umax, u);
        vmin = fminf(vmin, v); vmax = fmaxf(vmax, v);
    }
    g_imgbox[n*4+0] = fminf(fmaxf(umin, 0.f), Wf);
    g_imgbox[n*4+1] = fminf(fmaxf(vmin, 0.f), Hf);
    g_imgbox[n*4+2] = fminf(fmaxf(umax, 0.f), Wf);
    g_imgbox[n*4+3] = fminf(fmaxf(vmax, 0.f), Hf);
}

// ---------------- ROI align: warp = (channel, pool-row), lanes over samples ---
__global__ void roi_kernel(const float* __restrict__ img_feat,
                           const float* __restrict__ bev_feat)
{
    int b = blockIdx.x;
    int isImg = (b < N_PROP);
    int n = b & (N_PROP - 1);

    const float* feat  = isImg ? img_feat : bev_feat;
    const float* boxes = isImg ? g_imgbox : g_bevbox;
    float* outp        = isImg ? g_roiA   : g_roiB;
    int H = isImg ? 360 : 700;
    int W = isImg ? 1200 : 800;

    __shared__ int   sx0[SS], sx1[SS];
    __shared__ float swx[SS];
    __shared__ int   sy0[SS], sy1[SS];   // pre-multiplied by W
    __shared__ float swy[SS];
    __shared__ float colsum[8][SS];

    int t = threadIdx.x;                 // 256 threads, 8 warps
    int warp = t >> 5, lane = t & 31;

    if (t < SS) {
        float bx1 = boxes[n*4+0] - 0.5f;
        float bx2 = boxes[n*4+2] - 0.5f;
        float g = ((float)t + 0.5f) / (float)SS;
        float xs = bx1 + g * (bx2 - bx1);
        float xf = fminf(fmaxf(floorf(xs), 0.f), (float)(W - 1));
        swx[t] = fminf(fmaxf(xs - xf, 0.f), 1.f);
        int xi = (int)xf;
        sx0[t] = xi;
        sx1[t] = min(xi + 1, W - 1);
    } else if (t < 2 * SS) {
        int tt = t - SS;
        float by1 = boxes[n*4+1] - 0.5f;
        float by2 = boxes[n*4+3] - 0.5f;
        float g = ((float)tt + 0.5f) / (float)SS;
        float ys = by1 + g * (by2 - by1);
        float yf = fminf(fmaxf(floorf(ys), 0.f), (float)(H - 1));
        swy[tt] = fminf(fmaxf(ys - yf, 0.f), 1.f);
        int yi = (int)yf;
        sy0[tt] = yi * W;
        sy1[tt] = min(yi + 1, H - 1) * W;
    }
    __syncthreads();

    // 224 tasks = 32 channels x 7 pool rows; warp w does tasks w, w+8, ...
    for (int task = warp; task < C_FEAT * ROI; task += 8) {
        int c  = task / ROI;
        int py = task % ROI;
        const float* fc = feat + (size_t)c * H * W;

        // zero this warp's colsum
        colsum[warp][lane < SS ? lane : 0] = 0.f;   // lanes 0..31 (lane>=42 never)
        if (lane < SS - 32) colsum[warp][32 + lane] = 0.f;
        __syncwarp();

        // 252 samples: s = lane + 32k, iy = s/42, ix = s%42
#pragma unroll
        for (int k = 0; k < 8; k++) {
            int s = lane + (k << 5);
            if (s < SR * SS) {
                int iy = s / SS;
                int ix = s - iy * SS;
                int gy = py * SR + iy;
                int ro0 = sy0[gy], ro1 = sy1[gy];
                float wy = swy[gy];
                int x0 = sx0[ix], x1 = sx1[ix];
                float wx = swx[ix];
                float f00 = fc[ro0 + x0], f01 = fc[ro0 + x1];
                float f10 = fc[ro1 + x0], f11 = fc[ro1 + x1];
                float top = f00 + (f01 - f00) * wx;
                float bot = f10 + (f11 - f10) * wx;
                atomicAdd(&colsum[warp][ix], top + (bot - top) * wy);
            }
        }
        __syncwarp();

        if (lane < ROI) {
            float s6 = 0.f;
#pragma unroll
            for (int j = 0; j < SR; j++) s6 += colsum[warp][lane * SR + j];
            outp[(size_t)n * D_FEAT + c * 49 + py * ROI + lane] = s6 * (1.f / 36.f);
        }
        __syncwarp();
    }
}

// ---------------- fuse --------------------------------------------------------
__global__ void fuse_kernel(const float* __restrict__ mi,
                            const float* __restrict__ mb)
{
    int i = blockIdx.x * blockDim.x + threadIdx.x;
    if (i >= N_PROP * D_FEAT) return;
    float a = mi[0], bm = mb[0];
    float inv = 1.f / (a + bm);
    g_fused[i] = (g_roiA[i] * a + g_roiB[i] * bm) * inv;
}

// ---------------- SGEMM: FFMA2, 8x8 microtile, double-buffered (R3 best) ------
template<int RELU>
__global__ __launch_bounds__(128)
void gemm_kernel(const float* __restrict__ A, const float* __restrict__ B,
                 const float* __restrict__ bias, float* __restrict__ C,
                 int M, int N, int K)
{
    const int BM = 64, BN = 128, BK = 16;
    __shared__ float As[2][BK][BM];
    __shared__ float Bs[2][BK][BN];

    int tid = threadIdx.x;
    int tx = tid & 15;
    int ty = tid >> 4;
    int m0 = blockIdx.y * BM;
    int n0 = blockIdx.x * BN;

    int a_row0 = tid >> 2;
    int a_kc0  = (tid & 3) << 2;
    int a_row1 = (tid + 128) >> 2;
    int a_kc1  = ((tid + 128) & 3) << 2;
    int b_kk[4], b_c4[4];
#pragma unroll
    for (int l = 0; l < 4; l++) {
        int idx = tid + l * 128;
        b_kk[l] = idx >> 5;
        b_c4[l] = idx & 31;
    }

    unsigned long long acc2[8][4];
#pragma unroll
    for (int i = 0; i < 8; i++)
#pragma unroll
        for (int j = 0; j < 4; j++) acc2[i][j] = 0ULL;

    int nt = K / BK;

    {
        float4 v0 = *reinterpret_cast<const float4*>(A + (size_t)(m0 + a_row0) * K + a_kc0);
        float4 v1 = *reinterpret_cast<const float4*>(A + (size_t)(m0 + a_row1) * K + a_kc1);
        As[0][a_kc0 + 0][a_row0] = v0.x;
        As[0][a_kc0 + 1][a_row0] = v0.y;
        As[0][a_kc0 + 2][a_row0] = v0.z;
        As[0][a_kc0 + 3][a_row0] = v0.w;
        As[0][a_kc1 + 0][a_row1] = v1.x;
        As[0][a_kc1 + 1][a_row1] = v1.y;
        As[0][a_kc1 + 2][a_row1] = v1.z;
        As[0][a_kc1 + 3][a_row1] = v1.w;
#pragma unroll
        for (int l = 0; l < 4; l++) {
            *reinterpret_cast<float4*>(&Bs[0][b_kk[l]][b_c4[l] << 2]) =
                *reinterpret_cast<const float4*>(B + (size_t)b_kk[l] * N + n0 + (b_c4[l] << 2));
        }
    }
    __syncthreads();

    int buf = 0;
    for (int t = 0; t < nt; t++) {
        float4 ra0, ra1, rb[4];
        bool more = (t + 1 < nt);
        if (more) {
            int k0 = (t + 1) * BK;
            ra0 = *reinterpret_cast<const float4*>(A + (size_t)(m0 + a_row0) * K + k0 + a_kc0);
            ra1 = *reinterpret_cast<const float4*>(A + (size_t)(m0 + a_row1) * K + k0 + a_kc1);
#pragma unroll
            for (int l = 0; l < 4; l++)
                rb[l] = *reinterpret_cast<const float4*>(
                    B + (size_t)(k0 + b_kk[l]) * N + n0 + (b_c4[l] << 2));
        }

#pragma unroll
        for (int kk = 0; kk < BK; kk++) {
            float a[8];
            *reinterpret_cast<float4*>(a)     = *reinterpret_cast<const float4*>(&As[buf][kk][ty * 8]);
            *reinterpret_cast<float4*>(a + 4) = *reinterpret_cast<const float4*>(&As[buf][kk][ty * 8 + 4]);
            ulonglong2 b01 = *reinterpret_cast<const ulonglong2*>(&Bs[buf][kk][tx * 8]);
            ulonglong2 b23 = *reinterpret_cast<const ulonglong2*>(&Bs[buf][kk][tx * 8 + 4]);
            unsigned long long bp0 = b01.x, bp1 = b01.y, bp2 = b23.x, bp3 = b23.y;
#pragma unroll
            for (int i = 0; i < 8; i++) {
                unsigned long long ad;
                asm("mov.b64 %0, {%1, %1};" : "=l"(ad) : "f"(a[i]));
                asm("fma.rn.f32x2 %0, %1, %2, %0;" : "+l"(acc2[i][0]) : "l"(ad), "l"(bp0));
                asm("fma.rn.f32x2 %0, %1, %2, %0;" : "+l"(acc2[i][1]) : "l"(ad), "l"(bp1));
                asm("fma.rn.f32x2 %0, %1, %2, %0;" : "+l"(acc2[i][2]) : "l"(ad), "l"(bp2));
                asm("fma.rn.f32x2 %0, %1, %2, %0;" : "+l"(acc2[i][3]) : "l"(ad), "l"(bp3));
            }
        }

        if (more) {
            int nb = buf ^ 1;
            As[nb][a_kc0 + 0][a_row0] = ra0.x;
            As[nb][a_kc0 + 1][a_row0] = ra0.y;
            As[nb][a_kc0 + 2][a_row0] = ra0.z;
            As[nb][a_kc0 + 3][a_row0] = ra0.w;
            As[nb][a_kc1 + 0][a_row1] = ra1.x;
            As[nb][a_kc1 + 1][a_row1] = ra1.y;
            As[nb][a_kc1 + 2][a_row1] = ra1.z;
            As[nb][a_kc1 + 3][a_row1] = ra1.w;
#pragma unroll
            for (int l = 0; l < 4; l++)
                *reinterpret_cast<float4*>(&Bs[nb][b_kk[l]][b_c4[l] << 2]) = rb[l];
            __syncthreads();
            buf = nb;
        }
    }

    float4 bv0 = *reinterpret_cast<const float4*>(bias + n0 + tx * 8);
    float4 bv1 = *reinterpret_cast<const float4*>(bias + n0 + tx * 8 + 4);
#pragma unroll
    for (int i = 0; i < 8; i++) {
        int mrow = m0 + ty * 8 + i;
        float2 p0 = *reinterpret_cast<float2*>(&acc2[i][0]);
        float2 p1 = *reinterpret_cast<float2*>(&acc2[i][1]);
        float2 p2 = *reinterpret_cast<float2*>(&acc2[i][2]);
        float2 p3 = *reinterpret_cast<float2*>(&acc2[i][3]);
        float4 o0 = {p0.x + bv0.x, p0.y + bv0.y, p1.x + bv0.z, p1.y + bv0.w};
        float4 o1 = {p2.x + bv1.x, p2.y + bv1.y, p3.x + bv1.z, p3.y + bv1.w};
        if (RELU) {
            o0.x = fmaxf(o0.x, 0.f); o0.y = fmaxf(o0.y, 0.f);
            o0.z = fmaxf(o0.z, 0.f); o0.w = fmaxf(o0.w, 0.f);
            o1.x = fmaxf(o1.x, 0.f); o1.y = fmaxf(o1.y, 0.f);
            o1.z = fmaxf(o1.z, 0.f); o1.w = fmaxf(o1.w, 0.f);
        }
        *reinterpret_cast<float4*>(C + (size_t)mrow * N + n0 + tx * 8)     = o0;
        *reinterpret_cast<float4*>(C + (size_t)mrow * N + n0 + tx * 8 + 4) = o1;
    }
}

// ---------------- heads: warp per row, float2 W loads -------------------------
__global__ void heads_kernel(const float* __restrict__ Wc, const float* __restrict__ bc,
                             const float* __restrict__ Wo, const float* __restrict__ bo,
                             const float* __restrict__ Wa, const float* __restrict__ ba)
{
    int warp = threadIdx.x >> 5;
    int lane = threadIdx.x & 31;
    int row = blockIdx.x * 8 + warp;

    const float2* Wc2 = reinterpret_cast<const float2*>(Wc);
    const float2* Wo2 = reinterpret_cast<const float2*>(Wo);
    const float2* Wa2 = reinterpret_cast<const float2*>(Wa);

    float acc[14];
#pragma unroll
    for (int c = 0; c < 14; c++) acc[c] = 0.f;

    const float* h = g_h2 + (size_t)row * HID;
    for (int k = lane; k < HID; k += 32) {
        float hv = h[k];
        float2 cw = Wc2[k];
        acc[0] = fmaf(hv, cw.x, acc[0]);
        acc[1] = fmaf(hv, cw.y, acc[1]);
        const float2* wo = Wo2 + (size_t)k * 5;
#pragma unroll
        for (int j = 0; j < 5; j++) {
            float2 ov = wo[j];
            acc[2 + 2*j]     = fmaf(hv, ov.x, acc[2 + 2*j]);
            acc[2 + 2*j + 1] = fmaf(hv, ov.y, acc[2 + 2*j + 1]);
        }
        float2 aw = Wa2[k];
        acc[12] = fmaf(hv, aw.x, acc[12]);
        acc[13] = fmaf(hv, aw.y, acc[13]);
    }
#pragma unroll
    for (int c = 0; c < 14; c++) {
#pragma unroll
        for (int off = 16; off > 0; off >>= 1)
            acc[c] += __shfl_down_sync(0xffffffffu, acc[c], off);
    }
    if (lane == 0) {
#pragma unroll
        for (int c = 0; c < 14; c++) {
            float b = (c < 2) ? bc[c] : (c < 12 ? bo[c-2] : ba[c-12]);
            g_heads[row*14 + c] = acc[c] + b;
        }
    }
}

// ---------------- post ---------------------------------------------------------
__global__ void post_kernel(const float* __restrict__ anchors)
{
    int n = blockIdx.x * blockDim.x + threadIdx.x;
    if (n >= N_PROP) return;
    const float* hd = g_heads + n * 14;
    float o0 = hd[0], o1 = hd[1];
    float m = fmaxf(o0, o1);
    float e0 = expf(o0 - m), e1 = expf(o1 - m);
    float inv = 1.f / (e0 + e1);
    g_obj_soft[n*2+0] = e0 * inv;
    g_obj_soft[n*2+1] = e1 * inv;
    g_scores[n] = o1;
    g_orient[n] = atan2f(hd[13], hd[12]);

    float p[6];
#pragma unroll
    for (int i = 0; i < 6; i++) {
        p[i] = anchors[n*6+i] + hd[2+i];
        g_pred[n*6+i] = p[i];
    }
    float x = p[0], z = p[2], dx = p[3], dz = p[5];
    g_predbev[n*4+0] = (x - dx*0.5f - X_MIN) / VOX;
    g_predbev[n*4+1] = (Z_MAX - (z + dz*0.5f)) / VOX;
    g_predbev[n*4+2] = (x + dx*0.5f - X_MIN) / VOX;
    g_predbev[n*4+3] = (Z_MAX - (z - dz*0.5f)) / VOX;
}

// ---------------- NMS: 256 threads, 4 boxes/thread ----------------------------
__global__ void nms_kernel()
{
    int t = threadIdx.x;
    __shared__ float ss[N_PROP];
    __shared__ float sval[8];
    __shared__ int   sidx[8];
    __shared__ float sb[4];
    __shared__ int   scur;

    float bx1[4], by1[4], bx2[4], by2[4], bar[4];
#pragma unroll
    for (int i = 0; i < 4; i++) {
        int b = t + i * 256;
        bx1[i] = g_predbev[b*4+0];
        by1[i] = g_predbev[b*4+1];
        bx2[i] = g_predbev[b*4+2];
        by2[i] = g_predbev[b*4+3];
        bar[i] = (bx2[i] - bx1[i]) * (by2[i] - by1[i]);
        ss[b] = g_scores[b];
    }
    __syncthreads();

    int warp = t >> 5, lane = t & 31;
    for (int k = 0; k < NMS_K; k++) {
        float v = -INFINITY;
        int bi = N_PROP;
#pragma unroll
        for (int i = 0; i < 4; i++) {
            int b = t + i * 256;
            float s = ss[b];
            if (s > v) { v = s; bi = b; }
        }
#pragma unroll
        for (int off = 16; off > 0; off >>= 1) {
            float ov = __shfl_down_sync(0xffffffffu, v, off);
            int   oi = __shfl_down_sync(0xffffffffu, bi, off);
            if (ov > v || (ov == v && oi < bi)) { v = ov; bi = oi; }
        }
        if (lane == 0) { sval[warp] = v; sidx[warp] = bi; }
        __syncthreads();
        if (t < 8) {
            v = sval[t]; bi = sidx[t];
#pragma unroll
            for (int off = 4; off > 0; off >>= 1) {
                float ov = __shfl_down_sync(0xffu, v, off, 8);
                int   oi = __shfl_down_sync(0xffu, bi, off, 8);
                if (ov > v || (ov == v && oi < bi)) { v = ov; bi = oi; }
            }
            if (t == 0) {
                scur = bi;
                g_idx[k] = bi;
                sb[0] = g_predbev[bi*4+0];
                sb[1] = g_predbev[bi*4+1];
                sb[2] = g_predbev[bi*4+2];
                sb[3] = g_predbev[bi*4+3];
            }
        }
        __syncthreads();
        float px1 = sb[0], py1 = sb[1], px2 = sb[2], py2 = sb[3];
        float parea = (px2 - px1) * (py2 - py1);
        int cur = scur;
#pragma unroll
        for (int i = 0; i < 4; i++) {
            int b = t + i * 256;
            float xx1 = fmaxf(bx1[i], px1);
            float yy1 = fmaxf(by1[i], py1);
            float xx2 = fminf(bx2[i], px2);
            float yy2 = fminf(by2[i], py2);
            float inter = fmaxf(xx2 - xx1, 0.f) * fmaxf(yy2 - yy1, 0.f);
            float iou = inter / (bar[i] + parea - inter + 1e-6f);
            if (iou > NMS_THRF || b == cur) ss[b] = -INFINITY;
        }
        __syncthreads();
    }
}

// ---------------- gather -------------------------------------------------------
__global__ void gather_kernel(float* __restrict__ out)
{
    int i = blockIdx.x * blockDim.x + threadIdx.x;
    if (i >= OUT_TOTAL) return;
    float v;
    if (i < 200) {
        int n = i / 2, c = i % 2;
        v = g_obj_soft[g_idx[n]*2 + c];
    } else if (i < 800) {
        int j = i - 200; int n = j / 6, c = j % 6;
        v = g_pred[g_idx[n]*6 + c];
    } else if (i < 1800) {
        int j = i - 800; int n = j / 10, c = j % 10;
        v = g_heads[g_idx[n]*14 + 2 + c];
    } else if (i < 2500) {
        int j = i - 1800; int n = j / 7, c = j % 7;
        v = (c < 6) ? g_pred[g_idx[n]*6 + c] : 0.f;
    } else {
        int n = i - 2500;
        v = g_orient[g_idx[n]];
    }
    out[i] = v;
}

// ---------------- launch --------------------------------------------------------
extern "C" void kernel_launch(void* const* d_in, const int* in_sizes, int n_in,
                              void* d_out, int out_size)
{
    const float* img_feat = (const float*)d_in[0];
    const float* bev_feat = (const float*)d_in[1];
    const float* anchors  = (const float*)d_in[2];
    const float* calib    = (const float*)d_in[3];
    const float* img_mask = (const float*)d_in[5];
    const float* bev_mask = (const float*)d_in[6];
    const float* W1 = (const float*)d_in[7];
    const float* b1 = (const float*)d_in[8];
    const float* W2 = (const float*)d_in[9];
    const float* b2 = (const float*)d_in[10];
    const float* Wc = (const float*)d_in[11];
    const float* bc = (const float*)d_in[12];
    const float* Wo = (const float*)d_in[13];
    const float* bo = (const float*)d_in[14];
    const float* Wa = (const float*)d_in[15];
    const float* ba = (const float*)d_in[16];
    const int* image_shape = (const int*)d_in[17];
    float* out = (float*)d_out;

    void *p_fused, *p_h1, *p_h2;
    cudaGetSymbolAddress(&p_fused, g_fused);
    cudaGetSymbolAddress(&p_h1, g_h1);
    cudaGetSymbolAddress(&p_h2, g_h2);

    project_kernel<<<8, 128>>>(anchors, calib, image_shape);

    roi_kernel<<<2 * N_PROP, 256>>>(img_feat, bev_feat);
    fuse_kernel<<<(N_PROP * D_FEAT + 255) / 256, 256>>>(img_mask, bev_mask);

    dim3 g1(HID / 128, N_PROP / 64);
    gemm_kernel<1><<<g1, 128>>>((const float*)p_fused, W1, b1, (float*)p_h1,
                                N_PROP, HID, D_FEAT);
    gemm_kernel<1><<<g1, 128>>>((const float*)p_h1, W2, b2, (float*)p_h2,
                                N_PROP, HID, HID);

    heads_kernel<<<N_PROP / 8, 256>>>(Wc, bc, Wo, bo, Wa, ba);
    post_kernel<<<8, 128>>>(anchors);
    nms_kernel<<<1, 256>>>();
    gather_kernel<<<(OUT_TOTAL + 255) / 256, 256>>>(out);
}

// round 6
// speedup vs baseline: 1.2687x; 1.1364x over previous
#include <cuda_runtime.h>
#include <math.h>
#include <stdint.h>

#define N_PROP 1024
#define C_FEAT 32
#define ROI 7
#define SR 6
#define SS 42
#define D_FEAT 1568
#define HID 2048
#define NMS_K 100
#define OUT_TOTAL 2600
#define NMS_THRF 0.01f

#define IMG_H 360
#define IMG_W 1200
#define BEV_H 700
#define BEV_W 800
#define IMG_HW (IMG_H * IMG_W)
#define BEV_HW (BEV_H * BEV_W)

#define X_MIN (-40.0f)
#define Z_MAX (70.0f)
#define VOX (0.1f)

// ---------------- scratch ----------------------------------------------------
__device__ float g_imgbox[N_PROP * 4];
__device__ float g_bevbox[N_PROP * 4];
__device__ float g_imgT[IMG_HW * C_FEAT];   // HWC
__device__ float g_bevT[BEV_HW * C_FEAT];   // HWC
__device__ float g_roiA[N_PROP * D_FEAT];
__device__ float g_roiB[N_PROP * D_FEAT];
__device__ float g_fused[N_PROP * D_FEAT];
__device__ float g_h1[N_PROP * HID];
__device__ float g_h2[N_PROP * HID];
__device__ float g_heads[N_PROP * 14];
__device__ float g_obj_soft[N_PROP * 2];
__device__ float g_pred[N_PROP * 6];
__device__ float g_predbev[N_PROP * 4];
__device__ float g_scores[N_PROP];
__device__ float g_orient[N_PROP];
__device__ int   g_idx[NMS_K];

// ---------------- projections ------------------------------------------------
__global__ void project_kernel(const float* __restrict__ anchors,
                               const float* __restrict__ calib,
                               const int* __restrict__ image_shape)
{
    int n = blockIdx.x * blockDim.x + threadIdx.x;
    if (n >= N_PROP) return;
    const float* a = anchors + n * 6;
    float x = a[0], y = a[1], z = a[2];
    float dx = a[3], dy = a[4], dz = a[5];

    g_bevbox[n*4+0] = (x - dx*0.5f - X_MIN) / VOX;
    g_bevbox[n*4+1] = (Z_MAX - (z + dz*0.5f)) / VOX;
    g_bevbox[n*4+2] = (x + dx*0.5f - X_MIN) / VOX;
    g_bevbox[n*4+3] = (Z_MAX - (z - dz*0.5f)) / VOX;

    float P[12];
#pragma unroll
    for (int i = 0; i < 12; i++) P[i] = calib[i];
    float Hf = (float)image_shape[0];
    float Wf = (float)image_shape[1];

    float umin = 1e30f, umax = -1e30f, vmin = 1e30f, vmax = -1e30f;
#pragma unroll
    for (int k = 0; k < 8; k++) {
        float sx = (k & 4) ? 1.f : -1.f;
        float sy = (k & 2) ? 1.f : -1.f;
        float sz = (k & 1) ? 1.f : -1.f;
        float cx = x + sx * dx * 0.5f;
        float cy = y + sy * dy * 0.5f;
        float cz = z + sz * dz * 0.5f;
        float px = P[0]*cx + P[1]*cy + P[2]*cz + P[3];
        float py = P[4]*cx + P[5]*cy + P[6]*cz + P[7];
        float pz = P[8]*cx + P[9]*cy + P[10]*cz + P[11];
        float zz = fmaxf(pz, 0.1f);
        float u = px / zz, v = py / zz;
        umin = fminf(umin, u); umax = fmaxf(umax, u);
        vmin = fminf(vmin, v); vmax = fmaxf(vmax, v);
    }
    g_imgbox[n*4+0] = fminf(fmaxf(umin, 0.f), Wf);
    g_imgbox[n*4+1] = fminf(fmaxf(vmin, 0.f), Hf);
    g_imgbox[n*4+2] = fminf(fmaxf(umax, 0.f), Wf);
    g_imgbox[n*4+3] = fminf(fmaxf(vmax, 0.f), Hf);
}

// ---------------- CHW -> HWC transpose ---------------------------------------
// Block = 64 pixels x 32 channels tile. img: 6750 blocks, bev: 8750 blocks.
#define IMG_TILES (IMG_HW / 64)
#define BEV_TILES (BEV_HW / 64)
__global__ void transpose_kernel(const float* __restrict__ img,
                                 const float* __restrict__ bev)
{
    int b = blockIdx.x;
    const float* src;
    float* dst;
    int HW, p0;
    if (b < IMG_TILES) { src = img; dst = g_imgT; HW = IMG_HW; p0 = b * 64; }
    else               { src = bev; dst = g_bevT; HW = BEV_HW; p0 = (b - IMG_TILES) * 64; }

    __shared__ float tile[32][65];
    int t = threadIdx.x;      // 256

#pragma unroll
    for (int i = 0; i < 2; i++) {
        int idx = t + i * 256;          // 0..511 float4 ids
        int c   = idx >> 4;             // 0..31
        int v4  = idx & 15;             // 0..15
        float4 v = *reinterpret_cast<const float4*>(src + (size_t)c * HW + p0 + v4 * 4);
        tile[c][v4*4+0] = v.x;
        tile[c][v4*4+1] = v.y;
        tile[c][v4*4+2] = v.z;
        tile[c][v4*4+3] = v.w;
    }
    __syncthreads();
#pragma unroll
    for (int i = 0; i < 2; i++) {
        int idx = t + i * 256;
        int p   = idx >> 3;             // 0..63
        int c4  = idx & 7;              // 0..7
        float4 v;
        v.x = tile[c4*4+0][p];
        v.y = tile[c4*4+1][p];
        v.z = tile[c4*4+2][p];
        v.w = tile[c4*4+3][p];
        *reinterpret_cast<float4*>(dst + (size_t)(p0 + p) * 32 + c4 * 4) = v;
    }
}

// ---------------- ROI align on HWC: lane = channel ---------------------------
__global__ void roi_kernel()
{
    int b = blockIdx.x;            // 0..2047
    int isImg = (b < N_PROP);
    int n = b & (N_PROP - 1);

    const float* ft    = isImg ? g_imgT : g_bevT;
    const float* boxes = isImg ? g_imgbox : g_bevbox;
    float* outp        = isImg ? g_roiA : g_roiB;
    int H = isImg ? IMG_H : BEV_H;
    int W = isImg ? IMG_W : BEV_W;

    __shared__ int   sx0[SS], sx1[SS];     // premultiplied by 32
    __shared__ float swx[SS];
    __shared__ int   sy0[SS], sy1[SS];     // premultiplied by W*32
    __shared__ float swy[SS];
    __shared__ float sout[D_FEAT];         // c*49 + bin

    int t = threadIdx.x;                   // 256, 8 warps
    int warp = t >> 5, lane = t & 31;

    if (t < SS) {
        float bx1 = boxes[n*4+0] - 0.5f;
        float bx2 = boxes[n*4+2] - 0.5f;
        float g = ((float)t + 0.5f) / (float)SS;
        float xs = bx1 + g * (bx2 - bx1);
        float xf = fminf(fmaxf(floorf(xs), 0.f), (float)(W - 1));
        swx[t] = fminf(fmaxf(xs - xf, 0.f), 1.f);
        int xi = (int)xf;
        sx0[t] = xi * 32;
        sx1[t] = min(xi + 1, W - 1) * 32;
    } else if (t < 2 * SS) {
        int tt = t - SS;
        float by1 = boxes[n*4+1] - 0.5f;
        float by2 = boxes[n*4+3] - 0.5f;
        float g = ((float)tt + 0.5f) / (float)SS;
        float ys = by1 + g * (by2 - by1);
        float yf = fminf(fmaxf(floorf(ys), 0.f), (float)(H - 1));
        swy[tt] = fminf(fmaxf(ys - yf, 0.f), 1.f);
        int yi = (int)yf;
        sy0[tt] = yi * W * 32;
        sy1[tt] = min(yi + 1, H - 1) * W * 32;
    }
    __syncthreads();

    const float* fl = ft + lane;           // per-lane channel pointer

    // 49 bins; warp w handles bins w, w+8, ...
    for (int bin = warp; bin < ROI * ROI; bin += 8) {
        int py = (bin / ROI) * SR;
        int px = (bin % ROI) * SR;
        float acc = 0.f;
#pragma unroll
        for (int iy = 0; iy < SR; iy++) {
            int gy = py + iy;
            int ro0 = sy0[gy], ro1 = sy1[gy];
            float wy = swy[gy];
#pragma unroll
            for (int ix = 0; ix < SR; ix++) {
                int gx = px + ix;
                int c0 = sx0[gx], c1 = sx1[gx];
                float wx = swx[gx];
                float f00 = fl[ro0 + c0], f01 = fl[ro0 + c1];
                float f10 = fl[ro1 + c0], f11 = fl[ro1 + c1];
                float top = f00 + (f01 - f00) * wx;
                float bot = f10 + (f11 - f10) * wx;
                acc += top + (bot - top) * wy;
            }
        }
        sout[lane * 49 + bin] = acc * (1.f / 36.f);
    }
    __syncthreads();

    // coalesced write-out
    float* dst = outp + (size_t)n * D_FEAT;
#pragma unroll
    for (int i = 0; i < D_FEAT / 256 + 1; i++) {
        int idx = t + i * 256;
        if (idx < D_FEAT) dst[idx] = sout[idx];
    }
}

// ---------------- fuse --------------------------------------------------------
__global__ void fuse_kernel(const float* __restrict__ mi,
                            const float* __restrict__ mb)
{
    int i = blockIdx.x * blockDim.x + threadIdx.x;
    if (i >= N_PROP * D_FEAT) return;
    float a = mi[0], bm = mb[0];
    float inv = 1.f / (a + bm);
    g_fused[i] = (g_roiA[i] * a + g_roiB[i] * bm) * inv;
}

// ---------------- SGEMM: FFMA2, 8x8 microtile, double-buffered (R3) -----------
template<int RELU>
__global__ __launch_bounds__(128)
void gemm_kernel(const float* __restrict__ A, const float* __restrict__ B,
                 const float* __restrict__ bias, float* __restrict__ C,
                 int M, int N, int K)
{
    const int BM = 64, BN = 128, BK = 16;
    __shared__ float As[2][BK][BM];
    __shared__ float Bs[2][BK][BN];

    int tid = threadIdx.x;
    int tx = tid & 15;
    int ty = tid >> 4;
    int m0 = blockIdx.y * BM;
    int n0 = blockIdx.x * BN;

    int a_row0 = tid >> 2;
    int a_kc0  = (tid & 3) << 2;
    int a_row1 = (tid + 128) >> 2;
    int a_kc1  = ((tid + 128) & 3) << 2;
    int b_kk[4], b_c4[4];
#pragma unroll
    for (int l = 0; l < 4; l++) {
        int idx = tid + l * 128;
        b_kk[l] = idx >> 5;
        b_c4[l] = idx & 31;
    }

    unsigned long long acc2[8][4];
#pragma unroll
    for (int i = 0; i < 8; i++)
#pragma unroll
        for (int j = 0; j < 4; j++) acc2[i][j] = 0ULL;

    int nt = K / BK;

    {
        float4 v0 = *reinterpret_cast<const float4*>(A + (size_t)(m0 + a_row0) * K + a_kc0);
        float4 v1 = *reinterpret_cast<const float4*>(A + (size_t)(m0 + a_row1) * K + a_kc1);
        As[0][a_kc0 + 0][a_row0] = v0.x;
        As[0][a_kc0 + 1][a_row0] = v0.y;
        As[0][a_kc0 + 2][a_row0] = v0.z;
        As[0][a_kc0 + 3][a_row0] = v0.w;
        As[0][a_kc1 + 0][a_row1] = v1.x;
        As[0][a_kc1 + 1][a_row1] = v1.y;
        As[0][a_kc1 + 2][a_row1] = v1.z;
        As[0][a_kc1 + 3][a_row1] = v1.w;
#pragma unroll
        for (int l = 0; l < 4; l++) {
            *reinterpret_cast<float4*>(&Bs[0][b_kk[l]][b_c4[l] << 2]) =
                *reinterpret_cast<const float4*>(B + (size_t)b_kk[l] * N + n0 + (b_c4[l] << 2));
        }
    }
    __syncthreads();

    int buf = 0;
    for (int t = 0; t < nt; t++) {
        float4 ra0, ra1, rb[4];
        bool more = (t + 1 < nt);
        if (more) {
            int k0 = (t + 1) * BK;
            ra0 = *reinterpret_cast<const float4*>(A + (size_t)(m0 + a_row0) * K + k0 + a_kc0);
            ra1 = *reinterpret_cast<const float4*>(A + (size_t)(m0 + a_row1) * K + k0 + a_kc1);
#pragma unroll
            for (int l = 0; l < 4; l++)
                rb[l] = *reinterpret_cast<const float4*>(
                    B + (size_t)(k0 + b_kk[l]) * N + n0 + (b_c4[l] << 2));
        }

#pragma unroll
        for (int kk = 0; kk < BK; kk++) {
            float a[8];
            *reinterpret_cast<float4*>(a)     = *reinterpret_cast<const float4*>(&As[buf][kk][ty * 8]);
            *reinterpret_cast<float4*>(a + 4) = *reinterpret_cast<const float4*>(&As[buf][kk][ty * 8 + 4]);
            ulonglong2 b01 = *reinterpret_cast<const ulonglong2*>(&Bs[buf][kk][tx * 8]);
            ulonglong2 b23 = *reinterpret_cast<const ulonglong2*>(&Bs[buf][kk][tx * 8 + 4]);
            unsigned long long bp0 = b01.x, bp1 = b01.y, bp2 = b23.x, bp3 = b23.y;
#pragma unroll
            for (int i = 0; i < 8; i++) {
                unsigned long long ad;
                asm("mov.b64 %0, {%1, %1};" : "=l"(ad) : "f"(a[i]));
                asm("fma.rn.f32x2 %0, %1, %2, %0;" : "+l"(acc2[i][0]) : "l"(ad), "l"(bp0));
                asm("fma.rn.f32x2 %0, %1, %2, %0;" : "+l"(acc2[i][1]) : "l"(ad), "l"(bp1));
                asm("fma.rn.f32x2 %0, %1, %2, %0;" : "+l"(acc2[i][2]) : "l"(ad), "l"(bp2));
                asm("fma.rn.f32x2 %0, %1, %2, %0;" : "+l"(acc2[i][3]) : "l"(ad), "l"(bp3));
            }
        }

        if (more) {
            int nb = buf ^ 1;
            As[nb][a_kc0 + 0][a_row0] = ra0.x;
            As[nb][a_kc0 + 1][a_row0] = ra0.y;
            As[nb][a_kc0 + 2][a_row0] = ra0.z;
            As[nb][a_kc0 + 3][a_row0] = ra0.w;
            As[nb][a_kc1 + 0][a_row1] = ra1.x;
            As[nb][a_kc1 + 1][a_row1] = ra1.y;
            As[nb][a_kc1 + 2][a_row1] = ra1.z;
            As[nb][a_kc1 + 3][a_row1] = ra1.w;
#pragma unroll
            for (int l = 0; l < 4; l++)
                *reinterpret_cast<float4*>(&Bs[nb][b_kk[l]][b_c4[l] << 2]) = rb[l];
            __syncthreads();
            buf = nb;
        }
    }

    float4 bv0 = *reinterpret_cast<const float4*>(bias + n0 + tx * 8);
    float4 bv1 = *reinterpret_cast<const float4*>(bias + n0 + tx * 8 + 4);
#pragma unroll
    for (int i = 0; i < 8; i++) {
        int mrow = m0 + ty * 8 + i;
        float2 p0 = *reinterpret_cast<float2*>(&acc2[i][0]);
        float2 p1 = *reinterpret_cast<float2*>(&acc2[i][1]);
        float2 p2 = *reinterpret_cast<float2*>(&acc2[i][2]);
        float2 p3 = *reinterpret_cast<float2*>(&acc2[i][3]);
        float4 o0 = {p0.x + bv0.x, p0.y + bv0.y, p1.x + bv0.z, p1.y + bv0.w};
        float4 o1 = {p2.x + bv1.x, p2.y + bv1.y, p3.x + bv1.z, p3.y + bv1.w};
        if (RELU) {
            o0.x = fmaxf(o0.x, 0.f); o0.y = fmaxf(o0.y, 0.f);
            o0.z = fmaxf(o0.z, 0.f); o0.w = fmaxf(o0.w, 0.f);
            o1.x = fmaxf(o1.x, 0.f); o1.y = fmaxf(o1.y, 0.f);
            o1.z = fmaxf(o1.z, 0.f); o1.w = fmaxf(o1.w, 0.f);
        }
        *reinterpret_cast<float4*>(C + (size_t)mrow * N + n0 + tx * 8)     = o0;
        *reinterpret_cast<float4*>(C + (size_t)mrow * N + n0 + tx * 8 + 4) = o1;
    }
}

// ---------------- heads: warp per row, float2 W loads -------------------------
__global__ void heads_kernel(const float* __restrict__ Wc, const float* __restrict__ bc,
                             const float* __restrict__ Wo, const float* __restrict__ bo,
                             const float* __restrict__ Wa, const float* __restrict__ ba)
{
    int warp = threadIdx.x >> 5;
    int lane = threadIdx.x & 31;
    int row = blockIdx.x * 8 + warp;

    const float2* Wc2 = reinterpret_cast<const float2*>(Wc);
    const float2* Wo2 = reinterpret_cast<const float2*>(Wo);
    const float2* Wa2 = reinterpret_cast<const float2*>(Wa);

    float acc[14];
#pragma unroll
    for (int c = 0; c < 14; c++) acc[c] = 0.f;

    const float* h = g_h2 + (size_t)row * HID;
    for (int k = lane; k < HID; k += 32) {
        float hv = h[k];
        float2 cw = Wc2[k];
        acc[0] = fmaf(hv, cw.x, acc[0]);
        acc[1] = fmaf(hv, cw.y, acc[1]);
        const float2* wo = Wo2 + (size_t)k * 5;
#pragma unroll
        for (int j = 0; j < 5; j++) {
            float2 ov = wo[j];
            acc[2 + 2*j]     = fmaf(hv, ov.x, acc[2 + 2*j]);
            acc[2 + 2*j + 1] = fmaf(hv, ov.y, acc[2 + 2*j + 1]);
        }
        float2 aw = Wa2[k];
        acc[12] = fmaf(hv, aw.x, acc[12]);
        acc[13] = fmaf(hv, aw.y, acc[13]);
    }
#pragma unroll
    for (int c = 0; c < 14; c++) {
#pragma unroll
        for (int off = 16; off > 0; off >>= 1)
            acc[c] += __shfl_down_sync(0xffffffffu, acc[c], off);
    }
    if (lane == 0) {
#pragma unroll
        for (int c = 0; c < 14; c++) {
            float b = (c < 2) ? bc[c] : (c < 12 ? bo[c-2] : ba[c-12]);
            g_heads[row*14 + c] = acc[c] + b;
        }
    }
}

// ---------------- post ---------------------------------------------------------
__global__ void post_kernel(const float* __restrict__ anchors)
{
    int n = blockIdx.x * blockDim.x + threadIdx.x;
    if (n >= N_PROP) return;
    const float* hd = g_heads + n * 14;
    float o0 = hd[0], o1 = hd[1];
    float m = fmaxf(o0, o1);
    float e0 = expf(o0 - m), e1 = expf(o1 - m);
    float inv = 1.f / (e0 + e1);
    g_obj_soft[n*2+0] = e0 * inv;
    g_obj_soft[n*2+1] = e1 * inv;
    g_scores[n] = o1;
    g_orient[n] = atan2f(hd[13], hd[12]);

    float p[6];
#pragma unroll
    for (int i = 0; i < 6; i++) {
        p[i] = anchors[n*6+i] + hd[2+i];
        g_pred[n*6+i] = p[i];
    }
    float x = p[0], z = p[2], dx = p[3], dz = p[5];
    g_predbev[n*4+0] = (x - dx*0.5f - X_MIN) / VOX;
    g_predbev[n*4+1] = (Z_MAX - (z + dz*0.5f)) / VOX;
    g_predbev[n*4+2] = (x + dx*0.5f - X_MIN) / VOX;
    g_predbev[n*4+3] = (Z_MAX - (z - dz*0.5f)) / VOX;
}

// ---------------- NMS: 256 threads, 4 boxes/thread ----------------------------
__global__ void nms_kernel()
{
    int t = threadIdx.x;
    __shared__ float ss[N_PROP];
    __shared__ float sval[8];
    __shared__ int   sidx[8];
    __shared__ float sb[4];
    __shared__ int   scur;

    float bx1[4], by1[4], bx2[4], by2[4], bar[4];
#pragma unroll
    for (int i = 0; i < 4; i++) {
        int b = t + i * 256;
        bx1[i] = g_predbev[b*4+0];
        by1[i] = g_predbev[b*4+1];
        bx2[i] = g_predbev[b*4+2];
        by2[i] = g_predbev[b*4+3];
        bar[i] = (bx2[i] - bx1[i]) * (by2[i] - by1[i]);
        ss[b] = g_scores[b];
    }
    __syncthreads();

    int warp = t >> 5, lane = t & 31;
    for (int k = 0; k < NMS_K; k++) {
        float v = -INFINITY;
        int bi = N_PROP;
#pragma unroll
        for (int i = 0; i < 4; i++) {
            int b = t + i * 256;
            float s = ss[b];
            if (s > v) { v = s; bi = b; }
        }
#pragma unroll
        for (int off = 16; off > 0; off >>= 1) {
            float ov = __shfl_down_sync(0xffffffffu, v, off);
            int   oi = __shfl_down_sync(0xffffffffu, bi, off);
            if (ov > v || (ov == v && oi < bi)) { v = ov; bi = oi; }
        }
        if (lane == 0) { sval[warp] = v; sidx[warp] = bi; }
        __syncthreads();
        if (t < 8) {
            v = sval[t]; bi = sidx[t];
#pragma unroll
            for (int off = 4; off > 0; off >>= 1) {
                float ov = __shfl_down_sync(0xffu, v, off, 8);
                int   oi = __shfl_down_sync(0xffu, bi, off, 8);
                if (ov > v || (ov == v && oi < bi)) { v = ov; bi = oi; }
            }
            if (t == 0) {
                scur = bi;
                g_idx[k] = bi;
                sb[0] = g_predbev[bi*4+0];
                sb[1] = g_predbev[bi*4+1];
                sb[2] = g_predbev[bi*4+2];
                sb[3] = g_predbev[bi*4+3];
            }
        }
        __syncthreads();
        float px1 = sb[0], py1 = sb[1], px2 = sb[2], py2 = sb[3];
        float parea = (px2 - px1) * (py2 - py1);
        int cur = scur;
#pragma unroll
        for (int i = 0; i < 4; i++) {
            int b = t + i * 256;
            float xx1 = fmaxf(bx1[i], px1);
            float yy1 = fmaxf(by1[i], py1);
            float xx2 = fminf(bx2[i], px2);
            float yy2 = fminf(by2[i], py2);
            float inter = fmaxf(xx2 - xx1, 0.f) * fmaxf(yy2 - yy1, 0.f);
            float iou = inter / (bar[i] + parea - inter + 1e-6f);
            if (iou > NMS_THRF || b == cur) ss[b] = -INFINITY;
        }
        __syncthreads();
    }
}

// ---------------- gather -------------------------------------------------------
__global__ void gather_kernel(float* __restrict__ out)
{
    int i = blockIdx.x * blockDim.x + threadIdx.x;
    if (i >= OUT_TOTAL) return;
    float v;
    if (i < 200) {
        int n = i / 2, c = i % 2;
        v = g_obj_soft[g_idx[n]*2 + c];
    } else if (i < 800) {
        int j = i - 200; int n = j / 6, c = j % 6;
        v = g_pred[g_idx[n]*6 + c];
    } else if (i < 1800) {
        int j = i - 800; int n = j / 10, c = j % 10;
        v = g_heads[g_idx[n]*14 + 2 + c];
    } else if (i < 2500) {
        int j = i - 1800; int n = j / 7, c = j % 7;
        v = (c < 6) ? g_pred[g_idx[n]*6 + c] : 0.f;
    } else {
        int n = i - 2500;
        v = g_orient[g_idx[n]];
    }
    out[i] = v;
}

// ---------------- launch --------------------------------------------------------
extern "C" void kernel_launch(void* const* d_in, const int* in_sizes, int n_in,
                              void* d_out, int out_size)
{
    const float* img_feat = (const float*)d_in[0];
    const float* bev_feat = (const float*)d_in[1];
    const float* anchors  = (const float*)d_in[2];
    const float* calib    = (const float*)d_in[3];
    const float* img_mask = (const float*)d_in[5];
    const float* bev_mask = (const float*)d_in[6];
    const float* W1 = (const float*)d_in[7];
    const float* b1 = (const float*)d_in[8];
    const float* W2 = (const float*)d_in[9];
    const float* b2 = (const float*)d_in[10];
    const float* Wc = (const float*)d_in[11];
    const float* bc = (const float*)d_in[12];
    const float* Wo = (const float*)d_in[13];
    const float* bo = (const float*)d_in[14];
    const float* Wa = (const float*)d_in[15];
    const float* ba = (const float*)d_in[16];
    const int* image_shape = (const int*)d_in[17];
    float* out = (float*)d_out;

    void *p_fused, *p_h1, *p_h2;
    cudaGetSymbolAddress(&p_fused, g_fused);
    cudaGetSymbolAddress(&p_h1, g_h1);
    cudaGetSymbolAddress(&p_h2, g_h2);

    project_kernel<<<8, 128>>>(anchors, calib, image_shape);
    transpose_kernel<<<IMG_TILES + BEV_TILES, 256>>>(img_feat, bev_feat);

    roi_kernel<<<2 * N_PROP, 256>>>();
    fuse_kernel<<<(N_PROP * D_FEAT + 255) / 256, 256>>>(img_mask, bev_mask);

    dim3 g1(HID / 128, N_PROP / 64);
    gemm_kernel<1><<<g1, 128>>>((const float*)p_fused, W1, b1, (float*)p_h1,
                                N_PROP, HID, D_FEAT);
    gemm_kernel<1><<<g1, 128>>>((const float*)p_h1, W2, b2, (float*)p_h2,
                                N_PROP, HID, HID);

    heads_kernel<<<N_PROP / 8, 256>>>(Wc, bc, Wo, bo, Wa, ba);
    post_kernel<<<8, 128>>>(anchors);
    nms_kernel<<<1, 256>>>();
    gather_kernel<<<(OUT_TOTAL + 255) / 256, 256>>>(out);
}